// round 14
// baseline (speedup 1.0000x reference)
#include <cuda_runtime.h>

#define BB    64
#define TC    288
#define TF    12
#define LMAX  300
#define DD    16
#define HH    4
#define HDIM  4
#define DFF   64
#define NLAY  4
#define FULL  0xffffffffu

// ---------------- device scratch ----------------
__device__ float g_x  [BB*TC*DD];
__device__ float g_q  [BB*TC*DD];
__device__ float g_K  [NLAY*BB*HH*LMAX*HDIM];
__device__ float g_V  [NLAY*BB*HH*LMAX*HDIM];
__device__ float g_WqT[NLAY*768];            // [l][e][c]   e*48+c
__device__ float g_WoT[NLAY*256];            // [l][e][d]   e*16+d
__device__ float g_W1T[NLAY*1024];           // [l][e][j]   e*64+j
__device__ float g_W2T[NLAY*1024];           // [l][j][d]   j*16+d

__device__ __forceinline__ int kidx(int l,int b,int h,int p,int d){
    return (((l*BB+b)*HH+h)*LMAX+p)*HDIM+d;
}

__device__ __forceinline__ float gsum16f(float v){
    v += __shfl_xor_sync(FULL, v, 8, 16);
    v += __shfl_xor_sync(FULL, v, 4, 16);
    v += __shfl_xor_sync(FULL, v, 2, 16);
    v += __shfl_xor_sync(FULL, v, 1, 16);
    return v;
}
__device__ __forceinline__ float lnorm16s(float v, float g, float b){
    float s1 = v, s2 = v*v;
    #pragma unroll
    for (int o=8;o>0;o>>=1){
        s1 += __shfl_xor_sync(FULL, s1, o, 16);
        s2 += __shfl_xor_sync(FULL, s2, o, 16);
    }
    float mu  = s1 * 0.0625f;
    float var = fmaf(s2, 0.0625f, -mu*mu);
    return (v - mu) * rsqrtf(var + 1e-5f) * g + b;
}

// ---------------- weight transpose prep ----------------
__global__ void prep_kernel(const float* __restrict__ Wqkv, const float* __restrict__ Wo,
                            const float* __restrict__ fW1,  const float* __restrict__ fW2){
    int tid = blockIdx.x*blockDim.x + threadIdx.x;
    int str = gridDim.x*blockDim.x;
    for (int i=tid;i<NLAY*768;i+=str){ int l=i/768, r=i%768, e=r/48, c=r%48;
        g_WqT[i] = Wqkv[(l*48+c)*16+e]; }
    for (int i=tid;i<NLAY*256;i+=str){ int l=i/256, r=i%256, e=r/16, d=r%16;
        g_WoT[i] = Wo[(l*16+d)*16+e]; }
    for (int i=tid;i<NLAY*1024;i+=str){ int l=i/1024, r=i%1024, e=r/64, j=r%64;
        g_W1T[i] = fW1[(l*64+j)*16+e]; }
    for (int i=tid;i<NLAY*1024;i+=str){ int l=i/1024, r=i%1024, j=r/16, d=r%16;
        g_W2T[i] = fW2[(l*16+d)*64+j]; }
}

// ---------------- fusion + layer-0 QKV ----------------
__global__ void fuse_kernel(const float* __restrict__ b1, const float* __restrict__ b2,
                            const float* __restrict__ b3, const float* __restrict__ fW,
                            const float* __restrict__ fb, const float* __restrict__ pe,
                            const float* __restrict__ bqkv){
    __shared__ __align__(16) float WfT[768];
    __shared__ __align__(16) float WT[768];
    __shared__ float fbs[16], bs[48];
    int tid = threadIdx.x;       // 256
    for (int i=tid;i<768;i+=256){ int e=i>>4, d=i&15; WfT[i] = fW[d*48+e]; }
    for (int i=tid;i<768;i+=256) WT[i] = g_WqT[i];
    if (tid<16) fbs[tid] = fb[tid];
    if (tid<48) bs[tid]  = bqkv[tid];
    __syncthreads();
    int idx = blockIdx.x*256 + tid;
    int row = idx >> 4, d = idx & 15;
    int i   = row % TC;
    int b   = row / TC;
    const float* r1 = b1 + row*16;
    const float* r2 = b2 + row*16;
    const float* r3 = b3 + row*16;
    float acc = fbs[d];
    #pragma unroll
    for (int e=0;e<16;e++) acc = fmaf(r1[e], WfT[e*16+d],      acc);
    #pragma unroll
    for (int e=0;e<16;e++) acc = fmaf(r2[e], WfT[(16+e)*16+d], acc);
    #pragma unroll
    for (int e=0;e<16;e++) acc = fmaf(r3[e], WfT[(32+e)*16+d], acc);
    acc += pe[i*16+d];
    g_x[idx] = acc;
    float aq=bs[d], ak=bs[16+d], av=bs[32+d];
    #pragma unroll
    for (int e=0;e<16;e++){
        float xe = __shfl_sync(FULL, acc, e, 16);
        aq = fmaf(xe, WT[e*48+d],    aq);
        ak = fmaf(xe, WT[e*48+16+d], ak);
        av = fmaf(xe, WT[e*48+32+d], av);
    }
    g_q[row*16+d] = aq;
    g_K[kidx(0,b,d>>2,i,d&3)] = ak;
    g_V[kidx(0,b,d>>2,i,d&3)] = av;
}

// ---------------- fused prefill: all 4 layers, one block per batch ----------------
#define PT   576
#define XS4  5          // float4 row stride for sX/sQ/sAtt (bank-conflict pad)
#define KS4  289        // float4 head stride for sK/sV (bank-conflict pad)
#define PRE_FLOATS (4*KS4*4*2 + 288*XS4*4*3 + 3072+1024+4096+4096 + 192+512+256+64)
#define PRE_SMEM   (PRE_FLOATS*4)

__global__ void __launch_bounds__(PT,1) prefill_kernel(
    const float* __restrict__ bqkv, const float* __restrict__ bo,
    const float* __restrict__ crossb,
    const float* __restrict__ l1g, const float* __restrict__ l1b,
    const float* __restrict__ l2g, const float* __restrict__ l2b,
    const float* __restrict__ l3g, const float* __restrict__ l3b,
    const float* __restrict__ fb1, const float* __restrict__ fb2){
    extern __shared__ __align__(16) float sm[];
    float4* sK4 = (float4*)sm;               // [h*KS4 + p]
    float4* sV4 = sK4 + 4*KS4;
    float4* sX4 = sV4 + 4*KS4;               // [row*XS4 + k]
    float4* sQ4 = sX4 + 288*XS4;
    float4* sA4 = sQ4 + 288*XS4;
    float*  sWq = (float*)(sA4 + 288*XS4);
    float*  sWo = sWq + 3072;
    float*  sW1 = sWo + 1024;
    float*  sW2 = sW1 + 4096;
    float*  sBq = sW2 + 4096;
    float*  sBo = sBq + 192;
    float*  sCb = sBo + 64;
    float*  sG1 = sCb + 64;  float* sB1 = sG1 + 64;
    float*  sG2 = sB1 + 64;  float* sB2 = sG2 + 64;
    float*  sG3 = sB2 + 64;  float* sB3 = sG3 + 64;
    float*  sF1 = sB3 + 64;
    float*  sF2 = sF1 + 256;
    int tid = threadIdx.x;
    int b   = blockIdx.x;

    for (int i=tid;i<3072;i+=PT) sWq[i]=g_WqT[i];
    for (int i=tid;i<1024;i+=PT) sWo[i]=g_WoT[i];
    for (int i=tid;i<4096;i+=PT) sW1[i]=g_W1T[i];
    for (int i=tid;i<4096;i+=PT) sW2[i]=g_W2T[i];
    for (int i=tid;i<192;i+=PT)  sBq[i]=bqkv[i];
    if (tid<64){
        sBo[tid]=bo[tid]; sCb[tid]=crossb[tid];
        sG1[tid]=l1g[tid]; sB1[tid]=l1b[tid];
        sG2[tid]=l2g[tid]; sB2[tid]=l2b[tid];
        sG3[tid]=l3g[tid]; sB3[tid]=l3b[tid];
        sF2[tid]=fb2[tid];
    }
    for (int i=tid;i<256;i+=PT) sF1[i]=fb1[i];
    for (int i=tid;i<1152;i+=PT){
        int h=i/288, p=i%288;
        sK4[h*KS4+p] = ((const float4*)g_K)[(b*4+h)*300 + p];
        sV4[h*KS4+p] = ((const float4*)g_V)[(b*4+h)*300 + p];
    }
    for (int i=tid;i<1152;i+=PT){
        int row=i>>2, k=i&3;
        sX4[row*XS4+k] = ((const float4*)g_x)[b*1152+i];
        sQ4[row*XS4+k] = ((const float4*)g_q)[b*1152+i];
    }
    __syncthreads();

    int u = tid & 1, row = tid >> 1, off = u*8;   // post mapping
    int ha = tid & 3, ra = tid >> 2;              // attn mapping

    for (int l=0;l<NLAY;l++){
        // ---- attention phase: thread handles (ra,ha) and (287-ra,ha) ----
        {
            const float4* Kh = sK4 + ha*KS4;
            const float4* Vh = sV4 + ha*KS4;
            #pragma unroll
            for (int pass=0;pass<2;pass++){
                int i = pass ? (287 - ra) : ra;
                float4 qv = sQ4[i*XS4 + ha];
                float q0=qv.x,q1=qv.y,q2=qv.z,q3=qv.w;
                float s=0.f,o0=0.f,o1=0.f,o2=0.f,o3=0.f;
                for (int j=0;j<=i;j++){
                    float4 k4=Kh[j];
                    float sc=(k4.x*q0+k4.y*q1+k4.z*q2+k4.w*q3)*0.5f;
                    float pr=__expf(sc);
                    float4 v4=Vh[j];
                    s+=pr;
                    o0=fmaf(pr,v4.x,o0); o1=fmaf(pr,v4.y,o1);
                    o2=fmaf(pr,v4.z,o2); o3=fmaf(pr,v4.w,o3);
                }
                float inv=1.f/s;
                sA4[i*XS4+ha]=make_float4(o0*inv,o1*inv,o2*inv,o3*inv);
            }
        }
        __syncthreads();
        // ---- post phase: 2 threads per row ----
        {
            float att[16];
            #pragma unroll
            for (int k=0;k<4;k++){
                float4 av = sA4[row*XS4+k];
                att[k*4]=av.x; att[k*4+1]=av.y; att[k*4+2]=av.z; att[k*4+3]=av.w;
            }
            float a[8];
            {
                float4 x0=sX4[row*XS4+u*2], x1=sX4[row*XS4+u*2+1];
                a[0]=x0.x;a[1]=x0.y;a[2]=x0.z;a[3]=x0.w;
                a[4]=x1.x;a[5]=x1.y;a[6]=x1.z;a[7]=x1.w;
            }
            #pragma unroll
            for (int k=0;k<8;k++) a[k]+=sBo[l*16+off+k];
            #pragma unroll
            for (int e=0;e<16;e++){
                float ae=att[e];
                const float* wo=&sWo[l*256+e*16+off];
                float4 w0=*(const float4*)&wo[0];
                float4 w1=*(const float4*)&wo[4];
                a[0]=fmaf(ae,w0.x,a[0]); a[1]=fmaf(ae,w0.y,a[1]);
                a[2]=fmaf(ae,w0.z,a[2]); a[3]=fmaf(ae,w0.w,a[3]);
                a[4]=fmaf(ae,w1.x,a[4]); a[5]=fmaf(ae,w1.y,a[5]);
                a[6]=fmaf(ae,w1.z,a[6]); a[7]=fmaf(ae,w1.w,a[7]);
            }
            // LN1 (pair) + cross
            {
                float s1=0.f,s2=0.f;
                #pragma unroll
                for (int k=0;k<8;k++){ s1+=a[k]; s2=fmaf(a[k],a[k],s2); }
                s1 += __shfl_xor_sync(FULL,s1,1); s2 += __shfl_xor_sync(FULL,s2,1);
                float mu=s1*0.0625f, rstd=rsqrtf(fmaf(s2,0.0625f,-mu*mu)+1e-5f);
                #pragma unroll
                for (int k=0;k<8;k++) a[k]=(a[k]-mu)*rstd*sG1[l*16+off+k]+sB1[l*16+off+k]+sCb[l*16+off+k];
            }
            // LN2 (pair)
            {
                float s1=0.f,s2=0.f;
                #pragma unroll
                for (int k=0;k<8;k++){ s1+=a[k]; s2=fmaf(a[k],a[k],s2); }
                s1 += __shfl_xor_sync(FULL,s1,1); s2 += __shfl_xor_sync(FULL,s2,1);
                float mu=s1*0.0625f, rstd=rsqrtf(fmaf(s2,0.0625f,-mu*mu)+1e-5f);
                #pragma unroll
                for (int k=0;k<8;k++) a[k]=(a[k]-mu)*rstd*sG2[l*16+off+k]+sB2[l*16+off+k];
            }
            // assemble full z via 8 pair shuffles
            float zf[16];
            #pragma unroll
            for (int k=0;k<8;k++){
                float r = __shfl_xor_sync(FULL, a[k], 1);
                zf[k]   = u ? r    : a[k];
                zf[8+k] = u ? a[k] : r;
            }
            // FFN1: own 32 hidden units j = u*32 .. u*32+31
            float h[32];
            #pragma unroll
            for (int jj=0;jj<32;jj++) h[jj]=sF1[l*64+u*32+jj];
            #pragma unroll
            for (int e=0;e<16;e++){
                float ze=zf[e];
                const float* w1=&sW1[l*1024+e*64+u*32];
                #pragma unroll
                for (int jj=0;jj<32;jj+=4){
                    float4 w=*(const float4*)&w1[jj];
                    h[jj]  =fmaf(ze,w.x,h[jj]);   h[jj+1]=fmaf(ze,w.y,h[jj+1]);
                    h[jj+2]=fmaf(ze,w.z,h[jj+2]); h[jj+3]=fmaf(ze,w.w,h[jj+3]);
                }
            }
            #pragma unroll
            for (int jj=0;jj<32;jj++) h[jj]=fmaxf(h[jj],0.f);
            // FFN2: partials over own 32 j for ALL 16 outputs; pair-combine
            float pl[8], ph[8];
            #pragma unroll
            for (int k=0;k<8;k++){ pl[k]=0.f; ph[k]=0.f; }
            #pragma unroll
            for (int jj=0;jj<32;jj++){
                float hj=h[jj];
                const float* w2=&sW2[l*1024+(u*32+jj)*16];
                float4 wA=*(const float4*)&w2[0];
                float4 wB=*(const float4*)&w2[4];
                float4 wC=*(const float4*)&w2[8];
                float4 wD=*(const float4*)&w2[12];
                pl[0]=fmaf(hj,wA.x,pl[0]); pl[1]=fmaf(hj,wA.y,pl[1]);
                pl[2]=fmaf(hj,wA.z,pl[2]); pl[3]=fmaf(hj,wA.w,pl[3]);
                pl[4]=fmaf(hj,wB.x,pl[4]); pl[5]=fmaf(hj,wB.y,pl[5]);
                pl[6]=fmaf(hj,wB.z,pl[6]); pl[7]=fmaf(hj,wB.w,pl[7]);
                ph[0]=fmaf(hj,wC.x,ph[0]); ph[1]=fmaf(hj,wC.y,ph[1]);
                ph[2]=fmaf(hj,wC.z,ph[2]); ph[3]=fmaf(hj,wC.w,ph[3]);
                ph[4]=fmaf(hj,wD.x,ph[4]); ph[5]=fmaf(hj,wD.y,ph[5]);
                ph[6]=fmaf(hj,wD.z,ph[6]); ph[7]=fmaf(hj,wD.w,ph[7]);
            }
            float f[8];
            #pragma unroll
            for (int k=0;k<8;k++){
                float own  = u ? ph[k] : pl[k];
                float send = u ? pl[k] : ph[k];
                float recv = __shfl_xor_sync(FULL, send, 1);
                f[k] = own + recv + sF2[l*16+off+k] + zf[off+k];
            }
            // LN3 (pair)
            {
                float s1=0.f,s2=0.f;
                #pragma unroll
                for (int k=0;k<8;k++){ s1+=f[k]; s2=fmaf(f[k],f[k],s2); }
                s1 += __shfl_xor_sync(FULL,s1,1); s2 += __shfl_xor_sync(FULL,s2,1);
                float mu=s1*0.0625f, rstd=rsqrtf(fmaf(s2,0.0625f,-mu*mu)+1e-5f);
                #pragma unroll
                for (int k=0;k<8;k++) f[k]=(f[k]-mu)*rstd*sG3[l*16+off+k]+sB3[l*16+off+k];
            }
            sX4[row*XS4+u*2]   = make_float4(f[0],f[1],f[2],f[3]);
            sX4[row*XS4+u*2+1] = make_float4(f[4],f[5],f[6],f[7]);
            if (l < NLAY-1){
                // full f via 8 pair shuffles, then own 24 qkv outputs for layer l+1
                float ff[16];
                #pragma unroll
                for (int k=0;k<8;k++){
                    float r = __shfl_xor_sync(FULL, f[k], 1);
                    ff[k]   = u ? r    : f[k];
                    ff[8+k] = u ? f[k] : r;
                }
                #pragma unroll
                for (int g=0; g<6; g++){
                    int c0 = u*24 + g*4;
                    float a0=sBq[(l+1)*48+c0+0], a1=sBq[(l+1)*48+c0+1];
                    float a2=sBq[(l+1)*48+c0+2], a3=sBq[(l+1)*48+c0+3];
                    #pragma unroll
                    for (int e=0;e<16;e++){
                        float fe=ff[e];
                        float4 w=*(const float4*)&sWq[(l+1)*768+e*48+c0];
                        a0=fmaf(fe,w.x,a0); a1=fmaf(fe,w.y,a1);
                        a2=fmaf(fe,w.z,a2); a3=fmaf(fe,w.w,a3);
                    }
                    float4 v4=make_float4(a0,a1,a2,a3);
                    if (c0 < 16){
                        sQ4[row*XS4 + (c0>>2)] = v4;
                    } else if (c0 < 32){
                        int hh=(c0-16)>>2;
                        sK4[hh*KS4+row] = v4;
                        ((float4*)g_K)[(((l+1)*BB+b)*HH+hh)*LMAX + row] = v4;
                    } else {
                        int hh=(c0-32)>>2;
                        sV4[hh*KS4+row] = v4;
                        ((float4*)g_V)[(((l+1)*BB+b)*HH+hh)*LMAX + row] = v4;
                    }
                }
            } else {
                ((float4*)g_x)[(b*TC+row)*4 + u*2]   = make_float4(f[0],f[1],f[2],f[3]);
                ((float4*)g_x)[(b*TC+row)*4 + u*2+1] = make_float4(f[4],f[5],f[6],f[7]);
            }
        }
        __syncthreads();
    }
}

// ---------------- decode: unchanged from R13 (full-warp split) ----------------
#define DEC_WFLOATS (3072+1024+4096+4096+192+64*8+256+64+64+64+256)
#define DEC_SMEM (9600*16 + (32+DEC_WFLOATS)*4)

__global__ void decode_kernel(const float* __restrict__ bqkv, const float* __restrict__ bo,
    const float* __restrict__ crossb,
    const float* __restrict__ l1g, const float* __restrict__ l1b,
    const float* __restrict__ l2g, const float* __restrict__ l2b,
    const float* __restrict__ l3g, const float* __restrict__ l3b,
    const float* __restrict__ fb1, const float* __restrict__ fb2,
    const float* __restrict__ pe,  const float* __restrict__ outW,
    const float* __restrict__ outb, float* __restrict__ out){
    extern __shared__ float4 sm4[];
    float4* K4   = sm4;              // [l][h][p]
    float4* V4   = sm4 + 4800;
    float*  atts = (float*)(sm4 + 9600);   // [2][16]
    float*  sWq  = atts + 32;
    float*  sWo  = sWq + 3072;
    float*  sW1  = sWo + 1024;
    float*  sW2  = sW1 + 4096;
    float*  sBq  = sW2 + 4096;
    float*  sBo  = sBq + 192;
    float*  sCb  = sBo + 64;
    float*  sG1  = sCb + 64;
    float*  sB1  = sG1 + 64;
    float*  sG2  = sB1 + 64;
    float*  sB2  = sG2 + 64;
    float*  sG3  = sB2 + 64;
    float*  sB3  = sG3 + 64;
    float*  sF1  = sB3 + 64;
    float*  sF2  = sF1 + 256;
    float*  xbuf = sF2 + 64;    // [4][16]
    float*  zbuf = xbuf + 64;   // [4][16]
    float*  hbuf = zbuf + 64;   // [4][64]
    int tid  = threadIdx.x;  // 128
    int lane = tid & 31, wh = tid >> 5;
    int half = lane >> 4;    // 0/1
    int b    = blockIdx.x;

    for (int i=tid;i<4608;i+=128){
        int l = i/1152, r = i%1152, h = r/288, pp = r%288;
        int dst = (l*4+h)*300 + pp;
        int src = ((l*64+b)*4+h)*300 + pp;
        K4[dst] = ((const float4*)g_K)[src];
        V4[dst] = ((const float4*)g_V)[src];
    }
    for (int i=tid;i<3072;i+=128) sWq[i] = g_WqT[i];
    for (int i=tid;i<1024;i+=128) sWo[i] = g_WoT[i];
    for (int i=tid;i<4096;i+=128) sW1[i] = g_W1T[i];
    for (int i=tid;i<4096;i+=128) sW2[i] = g_W2T[i];
    for (int i=tid;i<192;i+=128)  sBq[i] = bqkv[i];
    if (tid<64){
        sBo[tid]=bo[tid]; sCb[tid]=crossb[tid];
        sG1[tid]=l1g[tid]; sB1[tid]=l1b[tid];
        sG2[tid]=l2g[tid]; sB2[tid]=l2b[tid];
        sG3[tid]=l3g[tid]; sB3[tid]=l3b[tid];
        sF2[tid]=fb2[tid];
    }
    for (int i=tid;i<256;i+=128) sF1[i] = fb1[i];

    int d = lane & 15;
    float oW = outW[d];
    float w2s = gsum16f(oW*oW);
    float ob  = outb[0];
    float x = g_x[(b*TC + TC-1)*DD + d];
    float nt = gsum16f(x*oW) + ob;
    if (tid==0) out[b*TF+0] = fmaf(nt, w2s, ob);
    x = fmaf(nt, oW, pe[TC*DD + d]);
    if (lane < 16) xbuf[wh*16+d] = x;
    __syncthreads();

    int it = 0;
    for (int t=1;t<TF;t++){
        int p = TC - 1 + t;
        for (int l=0;l<NLAY;l++){
            int lq = lane & 15;
            int li = (lq < 12) ? lq : 11;
            int dd = li & 3;
            int c  = (li<4) ? wh*4+dd : ((li<8) ? 16+wh*4+dd : 32+wh*4+dd);
            float acc = half ? 0.f : sBq[l*48+c];
            const float* wq = sWq + l*768 + c;
            const float* xb = xbuf + wh*16;
            int e0 = half*8;
            #pragma unroll
            for (int e=0;e<8;e++) acc = fmaf(xb[e0+e], wq[(e0+e)*48], acc);
            acc += __shfl_xor_sync(FULL, acc, 16);
            int base = ((l*4+wh)*300 + p)*4;
            if (lane>=4 && lane<8)  ((float*)K4)[base + (lane-4)] = acc;
            if (lane>=8 && lane<12) ((float*)V4)[base + (lane-8)] = acc;
            __syncwarp();
            float q0 = __shfl_sync(FULL, acc, 0);
            float q1 = __shfl_sync(FULL, acc, 1);
            float q2 = __shfl_sync(FULL, acc, 2);
            float q3 = __shfl_sync(FULL, acc, 3);
            const float4* Kh = K4 + (l*4+wh)*300;
            const float4* Vh = V4 + (l*4+wh)*300;
            float s=0.f, o0=0.f, o1=0.f, o2=0.f, o3=0.f;
            for (int j=lane;j<=p;j+=32){
                float4 k4 = Kh[j];
                float sc = (k4.x*q0 + k4.y*q1 + k4.z*q2 + k4.w*q3) * 0.5f;
                float pr = __expf(sc);
                float4 v4 = Vh[j];
                s += pr;
                o0 = fmaf(pr, v4.x, o0); o1 = fmaf(pr, v4.y, o1);
                o2 = fmaf(pr, v4.z, o2); o3 = fmaf(pr, v4.w, o3);
            }
            #pragma unroll
            for (int off=16;off>0;off>>=1){
                s  += __shfl_xor_sync(FULL, s,  off);
                o0 += __shfl_xor_sync(FULL, o0, off);
                o1 += __shfl_xor_sync(FULL, o1, off);
                o2 += __shfl_xor_sync(FULL, o2, off);
                o3 += __shfl_xor_sync(FULL, o3, off);
            }
            float* ab = atts + (it&1)*16;
            if (lane==0){
                float inv = 1.f/s;
                ab[wh*4+0]=o0*inv; ab[wh*4+1]=o1*inv;
                ab[wh*4+2]=o2*inv; ab[wh*4+3]=o3*inv;
            }
            __syncthreads();
            const float* wo = sWo + l*256 + d;
            float ap = 0.f;
            #pragma unroll
            for (int e=0;e<8;e++) ap = fmaf(ab[e0+e], wo[(e0+e)*16], ap);
            ap += __shfl_xor_sync(FULL, ap, 16);
            float a = sBo[l*16+d] + x + ap;
            a = lnorm16s(a, sG1[l*16+d], sB1[l*16+d]);
            a += sCb[l*16+d];
            float z = lnorm16s(a, sG2[l*16+d], sB2[l*16+d]);
            if (lane < 16) zbuf[wh*16+d] = z;
            __syncwarp();
            const float* zb = zbuf + wh*16;
            const float* w1 = sW1 + l*1024;
            int j0 = half*16 + d;
            float hv0 = sF1[l*64+j0], hv1 = sF1[l*64+j0+32];
            #pragma unroll
            for (int e=0;e<16;e++){
                float ze = zb[e];
                hv0 = fmaf(ze, w1[e*64 + j0],      hv0);
                hv1 = fmaf(ze, w1[e*64 + j0 + 32], hv1);
            }
            hv0 = fmaxf(hv0, 0.f); hv1 = fmaxf(hv1, 0.f);
            hbuf[wh*64 + j0]      = hv0;
            hbuf[wh*64 + j0 + 32] = hv1;
            __syncwarp();
            const float* hb = hbuf + wh*64;
            const float* w2 = sW2 + l*1024;
            float fp0 = 0.f, fp1 = 0.f;
            #pragma unroll
            for (int jj=0;jj<16;jj++){
                int ja = jj*4 + half;
                int jb = jj*4 + 2 + half;
                fp0 = fmaf(hb[ja], w2[ja*16+d], fp0);
                fp1 = fmaf(hb[jb], w2[jb*16+d], fp1);
            }
            float fp = fp0 + fp1;
            fp += __shfl_xor_sync(FULL, fp, 16);
            float f = lnorm16s(sF2[l*16+d] + z + fp, sG3[l*16+d], sB3[l*16+d]);
            if (l < NLAY-1){
                x = f;
            } else {
                float nv = gsum16f(f*oW) + ob;
                if (tid==0) out[b*TF+t] = fmaf(nv, w2s, ob);
                x = fmaf(nv, oW, pe[(p+1)*DD + d]);
            }
            if (lane < 16) xbuf[wh*16+d] = x;
            __syncwarp();
            it++;
        }
    }
}

// ---------------- launch ----------------
extern "C" void kernel_launch(void* const* d_in, const int* in_sizes, int n_in,
                              void* d_out, int out_size){
    const float* b1     = (const float*)d_in[0];
    const float* b2     = (const float*)d_in[1];
    const float* b3     = (const float*)d_in[2];
    const float* fW     = (const float*)d_in[3];
    const float* fb     = (const float*)d_in[4];
    const float* pe     = (const float*)d_in[5];
    const float* Wqkv   = (const float*)d_in[6];
    const float* bqkv   = (const float*)d_in[7];
    const float* Wo     = (const float*)d_in[8];
    const float* bo     = (const float*)d_in[9];
    const float* crossb = (const float*)d_in[10];
    const float* l1g    = (const float*)d_in[11];
    const float* l1b    = (const float*)d_in[12];
    const float* l2g    = (const float*)d_in[13];
    const float* l2b    = (const float*)d_in[14];
    const float* l3g    = (const float*)d_in[15];
    const float* l3b    = (const float*)d_in[16];
    const float* fW1    = (const float*)d_in[17];
    const float* fb1    = (const float*)d_in[18];
    const float* fW2    = (const float*)d_in[19];
    const float* fb2    = (const float*)d_in[20];
    const float* outW   = (const float*)d_in[21];
    const float* outb   = (const float*)d_in[22];
    float* out = (float*)d_out;

    static int smem_set = 0;
    if (!smem_set){
        cudaFuncSetAttribute(decode_kernel,  cudaFuncAttributeMaxDynamicSharedMemorySize, DEC_SMEM);
        cudaFuncSetAttribute(prefill_kernel, cudaFuncAttributeMaxDynamicSharedMemorySize, PRE_SMEM);
        smem_set = 1;
    }

    prep_kernel<<<12,256>>>(Wqkv, Wo, fW1, fW2);
    fuse_kernel<<<1152,256>>>(b1, b2, b3, fW, fb, pe, bqkv);
    prefill_kernel<<<BB,PT,PRE_SMEM>>>(bqkv, bo, crossb, l1g,l1b,l2g,l2b,l3g,l3b, fb1, fb2);
    decode_kernel<<<BB,128,DEC_SMEM>>>(bqkv, bo, crossb, l1g,l1b,l2g,l2b,l3g,l3b,
                                       fb1, fb2, pe, outW, outb, out);
}

// round 15
// speedup vs baseline: 1.3480x; 1.3480x over previous
#include <cuda_runtime.h>

#define BB    64
#define TC    288
#define TF    12
#define LMAX  300
#define DD    16
#define HH    4
#define HDIM  4
#define DFF   64
#define NLAY  4
#define FULL  0xffffffffu

// ---------------- device scratch ----------------
__device__ float g_x  [BB*TC*DD];
__device__ float g_q  [BB*TC*DD];
__device__ float g_att[BB*TC*DD];
__device__ float g_K  [NLAY*BB*HH*LMAX*HDIM];
__device__ float g_V  [NLAY*BB*HH*LMAX*HDIM];
__device__ float g_WqT[NLAY*768];            // [l][e][c]   e*48+c
__device__ float g_WoT[NLAY*256];            // [l][e][d]   e*16+d
__device__ float g_W1T[NLAY*1024];           // [l][e][j]   e*64+j
__device__ float g_W2T[NLAY*1024];           // [l][j][d]   j*16+d

__device__ __forceinline__ int kidx(int l,int b,int h,int p,int d){
    return (((l*BB+b)*HH+h)*LMAX+p)*HDIM+d;
}

__device__ __forceinline__ float gsum16f(float v){
    v += __shfl_xor_sync(FULL, v, 8, 16);
    v += __shfl_xor_sync(FULL, v, 4, 16);
    v += __shfl_xor_sync(FULL, v, 2, 16);
    v += __shfl_xor_sync(FULL, v, 1, 16);
    return v;
}
__device__ __forceinline__ float lnorm16s(float v, float g, float b){
    float s1 = v, s2 = v*v;
    #pragma unroll
    for (int o=8;o>0;o>>=1){
        s1 += __shfl_xor_sync(FULL, s1, o, 16);
        s2 += __shfl_xor_sync(FULL, s2, o, 16);
    }
    float mu  = s1 * 0.0625f;
    float var = fmaf(s2, 0.0625f, -mu*mu);
    return (v - mu) * rsqrtf(var + 1e-5f) * g + b;
}

// ---------------- weight transpose prep (for prefill kernels) ----------------
__global__ void prep_kernel(const float* __restrict__ Wqkv, const float* __restrict__ Wo,
                            const float* __restrict__ fW1,  const float* __restrict__ fW2){
    int tid = blockIdx.x*blockDim.x + threadIdx.x;
    int str = gridDim.x*blockDim.x;
    for (int i=tid;i<NLAY*768;i+=str){ int l=i/768, r=i%768, e=r/48, c=r%48;
        g_WqT[i] = Wqkv[(l*48+c)*16+e]; }
    for (int i=tid;i<NLAY*256;i+=str){ int l=i/256, r=i%256, e=r/16, d=r%16;
        g_WoT[i] = Wo[(l*16+d)*16+e]; }
    for (int i=tid;i<NLAY*1024;i+=str){ int l=i/1024, r=i%1024, e=r/64, j=r%64;
        g_W1T[i] = fW1[(l*64+j)*16+e]; }
    for (int i=tid;i<NLAY*1024;i+=str){ int l=i/1024, r=i%1024, j=r/16, d=r%16;
        g_W2T[i] = fW2[(l*16+d)*64+j]; }
}

// ---------------- fusion + layer-0 QKV ----------------
__global__ void fuse_kernel(const float* __restrict__ b1, const float* __restrict__ b2,
                            const float* __restrict__ b3, const float* __restrict__ fW,
                            const float* __restrict__ fb, const float* __restrict__ pe,
                            const float* __restrict__ bqkv){
    __shared__ __align__(16) float WfT[768];
    __shared__ __align__(16) float WT[768];
    __shared__ float fbs[16], bs[48];
    int tid = threadIdx.x;       // 256
    for (int i=tid;i<768;i+=256){ int e=i>>4, d=i&15; WfT[i] = fW[d*48+e]; }
    for (int i=tid;i<768;i+=256) WT[i] = g_WqT[i];
    if (tid<16) fbs[tid] = fb[tid];
    if (tid<48) bs[tid]  = bqkv[tid];
    __syncthreads();
    int idx = blockIdx.x*256 + tid;
    int row = idx >> 4, d = idx & 15;
    int i   = row % TC;
    int b   = row / TC;
    const float* r1 = b1 + row*16;
    const float* r2 = b2 + row*16;
    const float* r3 = b3 + row*16;
    float acc = fbs[d];
    #pragma unroll
    for (int e=0;e<16;e++) acc = fmaf(r1[e], WfT[e*16+d],      acc);
    #pragma unroll
    for (int e=0;e<16;e++) acc = fmaf(r2[e], WfT[(16+e)*16+d], acc);
    #pragma unroll
    for (int e=0;e<16;e++) acc = fmaf(r3[e], WfT[(32+e)*16+d], acc);
    acc += pe[i*16+d];
    g_x[idx] = acc;
    float aq=bs[d], ak=bs[16+d], av=bs[32+d];
    #pragma unroll
    for (int e=0;e<16;e++){
        float xe = __shfl_sync(FULL, acc, e, 16);
        aq = fmaf(xe, WT[e*48+d],    aq);
        ak = fmaf(xe, WT[e*48+16+d], ak);
        av = fmaf(xe, WT[e*48+32+d], av);
    }
    g_q[row*16+d] = aq;
    g_K[kidx(0,b,d>>2,i,d&3)] = ak;
    g_V[kidx(0,b,d>>2,i,d&3)] = av;
}

// ---------------- prefill attention: 2 threads per row (key split) ----------------
__global__ void attn_kernel(int l){
    __shared__ float4 ks4[TC], vs4[TC];
    int b = blockIdx.x >> 2, h = blockIdx.x & 3;
    int tid = threadIdx.x;   // 576
    const float4* Kb = (const float4*)(g_K + kidx(l,b,h,0,0));
    const float4* Vb = (const float4*)(g_V + kidx(l,b,h,0,0));
    for (int i=tid;i<TC;i+=576){ ks4[i]=Kb[i]; vs4[i]=Vb[i]; }
    __syncthreads();
    int i = tid >> 1;        // row
    int u = tid & 1;         // key-parity half
    float4 qv = ((const float4*)g_q)[(b*TC+i)*4 + h];
    float q0=qv.x, q1=qv.y, q2=qv.z, q3=qv.w;
    float s=0.f, o0=0.f, o1=0.f, o2=0.f, o3=0.f;
    int jend = min(i|15, TC-1);
    for (int j=u;j<=jend;j+=2){
        float4 k4 = ks4[j];
        float sc = (k4.x*q0 + k4.y*q1 + k4.z*q2 + k4.w*q3) * 0.5f;
        float p  = __expf(sc);
        p = (j <= i) ? p : 0.f;
        float4 v4 = vs4[j];
        s += p;
        o0 = fmaf(p, v4.x, o0); o1 = fmaf(p, v4.y, o1);
        o2 = fmaf(p, v4.z, o2); o3 = fmaf(p, v4.w, o3);
    }
    s  += __shfl_xor_sync(FULL, s,  1);
    o0 += __shfl_xor_sync(FULL, o0, 1);
    o1 += __shfl_xor_sync(FULL, o1, 1);
    o2 += __shfl_xor_sync(FULL, o2, 1);
    o3 += __shfl_xor_sync(FULL, o3, 1);
    if (u==0){
        float inv = 1.0f/s;
        float4 r; r.x=o0*inv; r.y=o1*inv; r.z=o2*inv; r.w=o3*inv;
        ((float4*)g_att)[(b*TC+i)*4 + h] = r;
    }
}

// ---------------- post: 2 threads per row (R11/R13 best-measured) ----------------
#define ZSTR 17
#define HSTR 68
__global__ void post_kernel(int l, const float* __restrict__ bo, const float* __restrict__ crossb,
    const float* __restrict__ l1g, const float* __restrict__ l1b,
    const float* __restrict__ l2g, const float* __restrict__ l2b,
    const float* __restrict__ l3g, const float* __restrict__ l3b,
    const float* __restrict__ fb1, const float* __restrict__ fb2,
    const float* __restrict__ bqkv){
    __shared__ __align__(16) float WoT[256], W1T[1024], W2T[1024], WTn[768];
    __shared__ float bos[16], cbs[16], g1[16], bb1[16], g2[16], bb2[16], g3[16], bb3[16];
    __shared__ float fb1s[64], fb2s[16], bsn[48];
    __shared__ float zrow[64*ZSTR];
    __shared__ __align__(16) float hrow[64*HSTR];
    __shared__ float frow[64*ZSTR];
    int tid = threadIdx.x;   // 128 -> 64 rows per block
    for (int i=tid;i<256;i+=128)  WoT[i] = g_WoT[l*256+i];
    for (int i=tid;i<1024;i+=128) W1T[i] = g_W1T[l*1024+i];
    for (int i=tid;i<1024;i+=128) W2T[i] = g_W2T[l*1024+i];
    if (l < NLAY-1){
        for (int i=tid;i<768;i+=128) WTn[i] = g_WqT[(l+1)*768+i];
        if (tid<48) bsn[tid] = bqkv[(l+1)*48+tid];
    }
    if (tid<16){
        bos[tid]=bo[l*16+tid]; cbs[tid]=crossb[l*16+tid];
        g1[tid]=l1g[l*16+tid]; bb1[tid]=l1b[l*16+tid];
        g2[tid]=l2g[l*16+tid]; bb2[tid]=l2b[l*16+tid];
        g3[tid]=l3g[l*16+tid]; bb3[tid]=l3b[l*16+tid];
        fb2s[tid]=fb2[l*16+tid];
    }
    if (tid<64) fb1s[tid]=fb1[l*64+tid];
    __syncthreads();
    int u    = tid & 1;
    int lrow = tid >> 1;
    int row  = blockIdx.x*64 + lrow;   // grid 288
    int b = row / TC, i = row % TC;
    int off = u*8;

    float att[16];
    {
        const float4* ar = (const float4*)(g_att + row*16);
        #pragma unroll
        for (int k=0;k<4;k++){
            float4 av = ar[k];
            att[k*4+0]=av.x; att[k*4+1]=av.y; att[k*4+2]=av.z; att[k*4+3]=av.w;
        }
    }
    float a[8];
    {
        const float4* xr = (const float4*)(g_x + row*16);
        float4 x0 = xr[u*2+0], x1 = xr[u*2+1];
        a[0]=x0.x; a[1]=x0.y; a[2]=x0.z; a[3]=x0.w;
        a[4]=x1.x; a[5]=x1.y; a[6]=x1.z; a[7]=x1.w;
    }
    #pragma unroll
    for (int k=0;k<8;k++) a[k] += bos[off+k];
    #pragma unroll
    for (int e=0;e<16;e++){
        float ae = att[e];
        #pragma unroll
        for (int k=0;k<2;k++){
            float4 w = *(const float4*)&WoT[e*16+off+k*4];
            a[k*4+0]=fmaf(ae,w.x,a[k*4+0]); a[k*4+1]=fmaf(ae,w.y,a[k*4+1]);
            a[k*4+2]=fmaf(ae,w.z,a[k*4+2]); a[k*4+3]=fmaf(ae,w.w,a[k*4+3]);
        }
    }
    {
        float s1=0.f,s2=0.f;
        #pragma unroll
        for (int k=0;k<8;k++){ s1+=a[k]; s2=fmaf(a[k],a[k],s2); }
        s1 += __shfl_xor_sync(FULL,s1,1); s2 += __shfl_xor_sync(FULL,s2,1);
        float mu=s1*0.0625f, rstd=rsqrtf(fmaf(s2,0.0625f,-mu*mu)+1e-5f);
        #pragma unroll
        for (int k=0;k<8;k++) a[k] = (a[k]-mu)*rstd*g1[off+k] + bb1[off+k] + cbs[off+k];
    }
    {
        float s1=0.f,s2=0.f;
        #pragma unroll
        for (int k=0;k<8;k++){ s1+=a[k]; s2=fmaf(a[k],a[k],s2); }
        s1 += __shfl_xor_sync(FULL,s1,1); s2 += __shfl_xor_sync(FULL,s2,1);
        float mu=s1*0.0625f, rstd=rsqrtf(fmaf(s2,0.0625f,-mu*mu)+1e-5f);
        #pragma unroll
        for (int k=0;k<8;k++) a[k] = (a[k]-mu)*rstd*g2[off+k] + bb2[off+k];
    }
    #pragma unroll
    for (int k=0;k<8;k++) zrow[lrow*ZSTR+off+k] = a[k];
    __syncwarp();
    float zf[16];
    #pragma unroll
    for (int m=0;m<16;m++) zf[m] = zrow[lrow*ZSTR+m];
    float h[32];
    #pragma unroll
    for (int jj=0;jj<32;jj++) h[jj] = fb1s[u*32+jj];
    #pragma unroll
    for (int e=0;e<16;e++){
        float ze = zf[e];
        const float* w1 = &W1T[e*64 + u*32];
        #pragma unroll
        for (int jj=0;jj<32;jj++) h[jj] = fmaf(ze, w1[jj], h[jj]);
    }
    #pragma unroll
    for (int jj=0;jj<32;jj++) h[jj] = fmaxf(h[jj], 0.f);
    {
        float4* hw = (float4*)&hrow[lrow*HSTR + u*32];
        #pragma unroll
        for (int k=0;k<8;k++) hw[k] = make_float4(h[k*4+0],h[k*4+1],h[k*4+2],h[k*4+3]);
    }
    __syncwarp();
    float f[8];
    #pragma unroll
    for (int k=0;k<8;k++) f[k] = fb2s[off+k] + zf[off+k];
    const float* hb = &hrow[lrow*HSTR];
    #pragma unroll
    for (int j=0;j<64;j++){
        float hj = hb[j];
        #pragma unroll
        for (int k=0;k<8;k++) f[k] = fmaf(hj, W2T[j*16+off+k], f[k]);
    }
    {
        float s1=0.f,s2=0.f;
        #pragma unroll
        for (int k=0;k<8;k++){ s1+=f[k]; s2=fmaf(f[k],f[k],s2); }
        s1 += __shfl_xor_sync(FULL,s1,1); s2 += __shfl_xor_sync(FULL,s2,1);
        float mu=s1*0.0625f, rstd=rsqrtf(fmaf(s2,0.0625f,-mu*mu)+1e-5f);
        #pragma unroll
        for (int k=0;k<8;k++) f[k] = (f[k]-mu)*rstd*g3[off+k] + bb3[off+k];
    }
    {
        float4* xw = (float4*)(g_x + row*16 + off);
        xw[0] = make_float4(f[0],f[1],f[2],f[3]);
        xw[1] = make_float4(f[4],f[5],f[6],f[7]);
    }
    if (l < NLAY-1){
        #pragma unroll
        for (int k=0;k<8;k++) frow[lrow*ZSTR+off+k] = f[k];
        __syncwarp();
        float ff[16];
        #pragma unroll
        for (int m=0;m<16;m++) ff[m] = frow[lrow*ZSTR+m];
        int c0base = u*24;
        #pragma unroll
        for (int c0=0;c0<24;c0+=4){
            int c = c0base + c0;
            float a0=bsn[c+0], a1=bsn[c+1], a2=bsn[c+2], a3=bsn[c+3];
            #pragma unroll
            for (int e=0;e<16;e++){
                float fe = ff[e];
                float4 w = *(const float4*)&WTn[e*48+c];
                a0=fmaf(fe,w.x,a0); a1=fmaf(fe,w.y,a1); a2=fmaf(fe,w.z,a2); a3=fmaf(fe,w.w,a3);
            }
            float4 v4 = make_float4(a0,a1,a2,a3);
            if (c < 16){
                ((float4*)(g_q + row*16))[c>>2] = v4;
            } else if (c < 32){
                int hh = (c-16)>>2;
                ((float4*)g_K)[((l+1)*BB+b)*HH*LMAX + hh*LMAX + i] = v4;
            } else {
                int hh = (c-32)>>2;
                ((float4*)g_V)[((l+1)*BB+b)*HH*LMAX + hh*LMAX + i] = v4;
            }
        }
    }
}

// ---------------- decode: contiguous (row-major) weight layouts, float4 LDS ----------------
// padded strides: Wq rows 20 (16 used), Wo rows 20, W1 rows 20, W2 rows 68 (64 used)
#define DEC_WFLOATS (3840+1280+5120+4352+192+64*8+256+64+64+64+256)
#define DEC_SMEM (9600*16 + (32+DEC_WFLOATS)*4)

__global__ void decode_kernel(
    const float* __restrict__ Wqkv, const float* __restrict__ Wo,
    const float* __restrict__ fW1,  const float* __restrict__ fW2,
    const float* __restrict__ bqkv, const float* __restrict__ bo,
    const float* __restrict__ crossb,
    const float* __restrict__ l1g, const float* __restrict__ l1b,
    const float* __restrict__ l2g, const float* __restrict__ l2b,
    const float* __restrict__ l3g, const float* __restrict__ l3b,
    const float* __restrict__ fb1, const float* __restrict__ fb2,
    const float* __restrict__ pe,  const float* __restrict__ outW,
    const float* __restrict__ outb, float* __restrict__ out){
    extern __shared__ float4 sm4[];
    float4* K4   = sm4;              // [l][h][p]
    float4* V4   = sm4 + 4800;
    float*  atts = (float*)(sm4 + 9600);   // [2][16]
    float*  sWq  = atts + 32;    // [l][c(48) stride20][e]
    float*  sWo  = sWq + 3840;   // [l][d(16) stride20][e]
    float*  sW1  = sWo + 1280;   // [l][j(64) stride20][e]
    float*  sW2  = sW1 + 5120;   // [l][d(16) stride68][j]
    float*  sBq  = sW2 + 4352;
    float*  sBo  = sBq + 192;
    float*  sCb  = sBo + 64;
    float*  sG1  = sCb + 64;
    float*  sB1  = sG1 + 64;
    float*  sG2  = sB1 + 64;
    float*  sB2  = sG2 + 64;
    float*  sG3  = sB2 + 64;
    float*  sB3  = sG3 + 64;
    float*  sF1  = sB3 + 64;
    float*  sF2  = sF1 + 256;
    float*  xbuf = sF2 + 64;    // [4][16]
    float*  zbuf = xbuf + 64;   // [4][16]
    float*  hbuf = zbuf + 64;   // [4][64]
    int tid  = threadIdx.x;  // 128
    int lane = tid & 31, wh = tid >> 5;
    int half = lane >> 4;    // 0/1
    int b    = blockIdx.x;

    for (int i=tid;i<4608;i+=128){
        int l = i/1152, r = i%1152, h = r/288, pp = r%288;
        int dst = (l*4+h)*300 + pp;
        int src = ((l*64+b)*4+h)*300 + pp;
        K4[dst] = ((const float4*)g_K)[src];
        V4[dst] = ((const float4*)g_V)[src];
    }
    for (int i=tid;i<3072;i+=128){ int l=i/768, r=i%768, c=r/16, e=r%16;
        sWq[l*960 + c*20 + e] = Wqkv[i]; }
    for (int i=tid;i<1024;i+=128){ int l=i/256, r=i%256, d=r/16, e=r%16;
        sWo[l*320 + d*20 + e] = Wo[i]; }
    for (int i=tid;i<4096;i+=128){ int l=i/1024, r=i%1024, j=r/16, e=r%16;
        sW1[l*1280 + j*20 + e] = fW1[i]; }
    for (int i=tid;i<4096;i+=128){ int l=i/1024, r=i%1024, d=r/64, j=r%64;
        sW2[l*1088 + d*68 + j] = fW2[i]; }
    for (int i=tid;i<192;i+=128)  sBq[i] = bqkv[i];
    if (tid<64){
        sBo[tid]=bo[tid]; sCb[tid]=crossb[tid];
        sG1[tid]=l1g[tid]; sB1[tid]=l1b[tid];
        sG2[tid]=l2g[tid]; sB2[tid]=l2b[tid];
        sG3[tid]=l3g[tid]; sB3[tid]=l3b[tid];
        sF2[tid]=fb2[tid];
    }
    for (int i=tid;i<256;i+=128) sF1[i] = fb1[i];

    int d = lane & 15;
    float oW = outW[d];
    float w2s = gsum16f(oW*oW);
    float ob  = outb[0];
    float x = g_x[(b*TC + TC-1)*DD + d];
    float nt = gsum16f(x*oW) + ob;
    if (tid==0) out[b*TF+0] = fmaf(nt, w2s, ob);
    x = fmaf(nt, oW, pe[TC*DD + d]);
    if (lane < 16) xbuf[wh*16+d] = x;
    __syncthreads();

    int it = 0;
    int e0 = half*8;
    for (int t=1;t<TF;t++){
        int p = TC - 1 + t;
        for (int l=0;l<NLAY;l++){
            // qkv: e-split across halves, contiguous weight rows
            int lq = lane & 15;
            int li = (lq < 12) ? lq : 11;
            int dd = li & 3;
            int c  = (li<4) ? wh*4+dd : ((li<8) ? 16+wh*4+dd : 32+wh*4+dd);
            float acc;
            {
                const float4* wq4 = (const float4*)&sWq[l*960 + c*20 + e0];
                const float4* xb4 = (const float4*)(xbuf + wh*16 + e0);
                float4 wA=wq4[0], wB=wq4[1], xA=xb4[0], xB=xb4[1];
                acc = half ? 0.f : sBq[l*48+c];
                acc = fmaf(xA.x,wA.x,acc); acc = fmaf(xA.y,wA.y,acc);
                acc = fmaf(xA.z,wA.z,acc); acc = fmaf(xA.w,wA.w,acc);
                acc = fmaf(xB.x,wB.x,acc); acc = fmaf(xB.y,wB.y,acc);
                acc = fmaf(xB.z,wB.z,acc); acc = fmaf(xB.w,wB.w,acc);
            }
            acc += __shfl_xor_sync(FULL, acc, 16);
            int base = ((l*4+wh)*300 + p)*4;
            if (lane>=4 && lane<8)  ((float*)K4)[base + (lane-4)] = acc;
            if (lane>=8 && lane<12) ((float*)V4)[base + (lane-8)] = acc;
            __syncwarp();
            float q0 = __shfl_sync(FULL, acc, 0);
            float q1 = __shfl_sync(FULL, acc, 1);
            float q2 = __shfl_sync(FULL, acc, 2);
            float q3 = __shfl_sync(FULL, acc, 3);
            const float4* Kh = K4 + (l*4+wh)*300;
            const float4* Vh = V4 + (l*4+wh)*300;
            float s=0.f, o0=0.f, o1=0.f, o2=0.f, o3=0.f;
            for (int j=lane;j<=p;j+=32){
                float4 k4 = Kh[j];
                float sc = (k4.x*q0 + k4.y*q1 + k4.z*q2 + k4.w*q3) * 0.5f;
                float pr = __expf(sc);
                float4 v4 = Vh[j];
                s += pr;
                o0 = fmaf(pr, v4.x, o0); o1 = fmaf(pr, v4.y, o1);
                o2 = fmaf(pr, v4.z, o2); o3 = fmaf(pr, v4.w, o3);
            }
            #pragma unroll
            for (int off=16;off>0;off>>=1){
                s  += __shfl_xor_sync(FULL, s,  off);
                o0 += __shfl_xor_sync(FULL, o0, off);
                o1 += __shfl_xor_sync(FULL, o1, off);
                o2 += __shfl_xor_sync(FULL, o2, off);
                o3 += __shfl_xor_sync(FULL, o3, off);
            }
            float* ab = atts + (it&1)*16;
            if (lane==0){
                float inv = 1.f/s;
                ab[wh*4+0]=o0*inv; ab[wh*4+1]=o1*inv;
                ab[wh*4+2]=o2*inv; ab[wh*4+3]=o3*inv;
            }
            __syncthreads();
            // out-proj: e-split, contiguous rows
            float ap;
            {
                const float4* wo4 = (const float4*)&sWo[l*320 + d*20 + e0];
                const float4* ab4 = (const float4*)(ab + e0);
                float4 wA=wo4[0], wB=wo4[1], aA=ab4[0], aB=ab4[1];
                ap  = aA.x*wA.x + aA.y*wA.y;
                ap  = fmaf(aA.z,wA.z,ap); ap = fmaf(aA.w,wA.w,ap);
                ap  = fmaf(aB.x,wB.x,ap); ap = fmaf(aB.y,wB.y,ap);
                ap  = fmaf(aB.z,wB.z,ap); ap = fmaf(aB.w,wB.w,ap);
            }
            ap += __shfl_xor_sync(FULL, ap, 16);
            float a = sBo[l*16+d] + x + ap;
            a = lnorm16s(a, sG1[l*16+d], sB1[l*16+d]);
            a += sCb[l*16+d];
            float z = lnorm16s(a, sG2[l*16+d], sB2[l*16+d]);
            if (lane < 16) zbuf[wh*16+d] = z;
            __syncwarp();
            // FFN1: hidden units j0=half*16+d and j0+32; contiguous weight rows
            int j0 = half*16 + d;
            float hv0, hv1;
            {
                const float4* zb4 = (const float4*)(zbuf + wh*16);
                float4 zA=zb4[0], zB=zb4[1], zC=zb4[2], zD=zb4[3];
                const float4* w1a = (const float4*)&sW1[l*1280 + j0*20];
                const float4* w1b = (const float4*)&sW1[l*1280 + (j0+32)*20];
                float4 a0=w1a[0],a1=w1a[1],a2=w1a[2],a3=w1a[3];
                float4 b0=w1b[0],b1=w1b[1],b2=w1b[2],b3=w1b[3];
                hv0 = sF1[l*64+j0];
                hv0=fmaf(zA.x,a0.x,hv0); hv0=fmaf(zA.y,a0.y,hv0); hv0=fmaf(zA.z,a0.z,hv0); hv0=fmaf(zA.w,a0.w,hv0);
                hv0=fmaf(zB.x,a1.x,hv0); hv0=fmaf(zB.y,a1.y,hv0); hv0=fmaf(zB.z,a1.z,hv0); hv0=fmaf(zB.w,a1.w,hv0);
                hv0=fmaf(zC.x,a2.x,hv0); hv0=fmaf(zC.y,a2.y,hv0); hv0=fmaf(zC.z,a2.z,hv0); hv0=fmaf(zC.w,a2.w,hv0);
                hv0=fmaf(zD.x,a3.x,hv0); hv0=fmaf(zD.y,a3.y,hv0); hv0=fmaf(zD.z,a3.z,hv0); hv0=fmaf(zD.w,a3.w,hv0);
                hv1 = sF1[l*64+j0+32];
                hv1=fmaf(zA.x,b0.x,hv1); hv1=fmaf(zA.y,b0.y,hv1); hv1=fmaf(zA.z,b0.z,hv1); hv1=fmaf(zA.w,b0.w,hv1);
                hv1=fmaf(zB.x,b1.x,hv1); hv1=fmaf(zB.y,b1.y,hv1); hv1=fmaf(zB.z,b1.z,hv1); hv1=fmaf(zB.w,b1.w,hv1);
                hv1=fmaf(zC.x,b2.x,hv1); hv1=fmaf(zC.y,b2.y,hv1); hv1=fmaf(zC.z,b2.z,hv1); hv1=fmaf(zC.w,b2.w,hv1);
                hv1=fmaf(zD.x,b3.x,hv1); hv1=fmaf(zD.y,b3.y,hv1); hv1=fmaf(zD.z,b3.z,hv1); hv1=fmaf(zD.w,b3.w,hv1);
            }
            hv0 = fmaxf(hv0, 0.f); hv1 = fmaxf(hv1, 0.f);
            hbuf[wh*64 + j0]      = hv0;
            hbuf[wh*64 + j0 + 32] = hv1;
            __syncwarp();
            // FFN2: contiguous j-range split (half0: j 0..31, half1: j 32..63)
            float fp;
            {
                const float4* hb4 = (const float4*)(hbuf + wh*64 + half*32);
                const float4* w24 = (const float4*)&sW2[l*1088 + d*68 + half*32];
                float fpA=0.f, fpB=0.f, fpC=0.f, fpD=0.f;
                #pragma unroll
                for (int k=0;k<2;k++){
                    float4 h0=hb4[k*4+0], h1=hb4[k*4+1], h2=hb4[k*4+2], h3=hb4[k*4+3];
                    float4 w0=w24[k*4+0], w1=w24[k*4+1], w2=w24[k*4+2], w3=w24[k*4+3];
                    fpA=fmaf(h0.x,w0.x,fpA); fpA=fmaf(h0.y,w0.y,fpA); fpA=fmaf(h0.z,w0.z,fpA); fpA=fmaf(h0.w,w0.w,fpA);
                    fpB=fmaf(h1.x,w1.x,fpB); fpB=fmaf(h1.y,w1.y,fpB); fpB=fmaf(h1.z,w1.z,fpB); fpB=fmaf(h1.w,w1.w,fpB);
                    fpC=fmaf(h2.x,w2.x,fpC); fpC=fmaf(h2.y,w2.y,fpC); fpC=fmaf(h2.z,w2.z,fpC); fpC=fmaf(h2.w,w2.w,fpC);
                    fpD=fmaf(h3.x,w3.x,fpD); fpD=fmaf(h3.y,w3.y,fpD); fpD=fmaf(h3.z,w3.z,fpD); fpD=fmaf(h3.w,w3.w,fpD);
                }
                fp = (fpA+fpB)+(fpC+fpD);
            }
            fp += __shfl_xor_sync(FULL, fp, 16);
            float f = lnorm16s(sF2[l*16+d] + z + fp, sG3[l*16+d], sB3[l*16+d]);
            if (l < NLAY-1){
                x = f;
            } else {
                float nv = gsum16f(f*oW) + ob;
                if (tid==0) out[b*TF+t] = fmaf(nv, w2s, ob);
                x = fmaf(nv, oW, pe[(p+1)*DD + d]);
            }
            if (lane < 16) xbuf[wh*16+d] = x;
            __syncwarp();
            it++;
        }
    }
}

// ---------------- launch ----------------
extern "C" void kernel_launch(void* const* d_in, const int* in_sizes, int n_in,
                              void* d_out, int out_size){
    const float* b1     = (const float*)d_in[0];
    const float* b2     = (const float*)d_in[1];
    const float* b3     = (const float*)d_in[2];
    const float* fW     = (const float*)d_in[3];
    const float* fb     = (const float*)d_in[4];
    const float* pe     = (const float*)d_in[5];
    const float* Wqkv   = (const float*)d_in[6];
    const float* bqkv   = (const float*)d_in[7];
    const float* Wo     = (const float*)d_in[8];
    const float* bo     = (const float*)d_in[9];
    const float* crossb = (const float*)d_in[10];
    const float* l1g    = (const float*)d_in[11];
    const float* l1b    = (const float*)d_in[12];
    const float* l2g    = (const float*)d_in[13];
    const float* l2b    = (const float*)d_in[14];
    const float* l3g    = (const float*)d_in[15];
    const float* l3b    = (const float*)d_in[16];
    const float* fW1    = (const float*)d_in[17];
    const float* fb1    = (const float*)d_in[18];
    const float* fW2    = (const float*)d_in[19];
    const float* fb2    = (const float*)d_in[20];
    const float* outW   = (const float*)d_in[21];
    const float* outb   = (const float*)d_in[22];
    float* out = (float*)d_out;

    static int smem_set = 0;
    if (!smem_set){
        cudaFuncSetAttribute(decode_kernel, cudaFuncAttributeMaxDynamicSharedMemorySize, DEC_SMEM);
        smem_set = 1;
    }

    prep_kernel<<<12,256>>>(Wqkv, Wo, fW1, fW2);
    fuse_kernel<<<1152,256>>>(b1, b2, b3, fW, fb, pe, bqkv);
    for (int l=0;l<NLAY;l++){
        attn_kernel<<<BB*HH,576>>>(l);
        post_kernel<<<288,128>>>(l, bo, crossb, l1g,l1b,l2g,l2b,l3g,l3b, fb1, fb2, bqkv);
    }
    decode_kernel<<<BB,128,DEC_SMEM>>>(Wqkv, Wo, fW1, fW2,
                                       bqkv, bo, crossb, l1g,l1b,l2g,l2b,l3g,l3b,
                                       fb1, fb2, pe, outW, outb, out);
}